// round 12
// baseline (speedup 1.0000x reference)
#include <cuda_runtime.h>
#include <cstdint>

#define BATCH 4
#define NPTS  8192
#define KNN   16
#define CIN   64
#define CO    64
#define F3    192
#define CS    20
#define PPT   4
#define NQ    (BATCH * NPTS)

// grid params
#define G     32
#define G3    (G * G * G)
#define HCELL 0.25f
#define HINV  4.0f
#define ORG   (-4.0f)

typedef unsigned long long ull;
typedef unsigned int uint;

__device__ int    g_idx[NQ * KNN];
__device__ float  g_feat3[(size_t)NQ * F3];
__device__ float  g_WgT[CO * CO];   // [c][o] = (w_gamma2 @ w_gamma1)^T
__device__ float  g_WtT[3 * CO];    // [c3][o] = (w_theta2 @ w_theta1)^T

// grid scratch
__device__ int    g_cnt[BATCH * G3];
__device__ int    g_cstart[BATCH * (G3 + 1)];
__device__ int    g_ccur[BATCH * G3];
__device__ int    g_cid[BATCH * NPTS];
__device__ float4 g_spt[BATCH * NPTS];   // cell-sorted points {x,y,z,|p|^2}
__device__ int    g_sid[BATCH * NPTS];   // original index of sorted point

// ---------------------------------------------------------------------------
// packed f32x2 helpers (fused kernel)
// ---------------------------------------------------------------------------
__device__ __forceinline__ ull pack2(float f) {
    ull r; uint u = __float_as_uint(f);
    asm("mov.b64 %0, {%1, %1};" : "=l"(r) : "r"(u));
    return r;
}
__device__ __forceinline__ void fma2(ull& acc, ull a, ull b) {
    asm("fma.rn.f32x2 %0, %1, %2, %0;" : "+l"(acc) : "l"(a), "l"(b));
}
__device__ __forceinline__ float f2lo(ull v) { return __uint_as_float((uint)v); }
__device__ __forceinline__ float f2hi(ull v) { return __uint_as_float((uint)(v >> 32)); }

// ---------------------------------------------------------------------------
__device__ __forceinline__ void insert16(float d, int id, float bd[KNN], int bi[KNN]) {
#pragma unroll
    for (int t = 0; t < KNN; ++t) {
        bool p = d < bd[t];
        float td = bd[t]; int ti = bi[t];
        bd[t] = p ? d : bd[t];
        bi[t] = p ? id : bi[t];
        d  = p ? td : d;
        id = p ? ti : id;
    }
}

// ---------------------------------------------------------------------------
// Grid build kernels
// ---------------------------------------------------------------------------
__global__ void __launch_bounds__(256) gzero() {
    int i = blockIdx.x * 256 + threadIdx.x;
    if (i < BATCH * G3) g_cnt[i] = 0;
}

__device__ __forceinline__ int cell_of(float x, float y, float z) {
    int cx = min(G - 1, max(0, (int)floorf((x - ORG) * HINV)));
    int cy = min(G - 1, max(0, (int)floorf((y - ORG) * HINV)));
    int cz = min(G - 1, max(0, (int)floorf((z - ORG) * HINV)));
    return (cz * G + cy) * G + cx;
}

__global__ void __launch_bounds__(256) gcount(const float* __restrict__ coords) {
    const int b = blockIdx.y;
    const int n = blockIdx.x * 256 + threadIdx.x;
    const float* cb = coords + (size_t)b * 3 * NPTS;
    float x = cb[n], y = cb[NPTS + n], z = cb[2 * NPTS + n];
    int cid = cell_of(x, y, z);
    g_cid[b * NPTS + n] = cid;
    atomicAdd(&g_cnt[b * G3 + cid], 1);
}

// per-batch exclusive prefix scan over G3 counts (1024 threads x 32 cells)
__global__ void __launch_bounds__(1024) gscan() {
    __shared__ int part[1024];
    const int b = blockIdx.x;
    const int t = threadIdx.x;
    const int base = b * G3 + t * 32;

    int s = 0;
#pragma unroll 8
    for (int i = 0; i < 32; ++i) s += g_cnt[base + i];
    part[t] = s;
    __syncthreads();
    for (int off = 1; off < 1024; off <<= 1) {
        int v = (t >= off) ? part[t - off] : 0;
        __syncthreads();
        part[t] += v;
        __syncthreads();
    }
    int run = part[t] - s;   // exclusive prefix of this thread's chunk
    const int obase = b * (G3 + 1) + t * 32;
#pragma unroll 8
    for (int i = 0; i < 32; ++i) {
        int c = g_cnt[base + i];
        g_cstart[obase + i] = run;
        g_ccur[base + i] = run;
        run += c;
    }
    if (t == 1023) g_cstart[b * (G3 + 1) + G3] = part[1023];
}

__global__ void __launch_bounds__(256) gfill(const float* __restrict__ coords) {
    const int b = blockIdx.y;
    const int n = blockIdx.x * 256 + threadIdx.x;
    const float* cb = coords + (size_t)b * 3 * NPTS;
    float x = cb[n], y = cb[NPTS + n], z = cb[2 * NPTS + n];
    int cid = g_cid[b * NPTS + n];
    int pos = atomicAdd(&g_ccur[b * G3 + cid], 1);
    float nrm = fmaf(z, z, fmaf(y, y, x * x));
    g_spt[b * NPTS + pos] = make_float4(x, y, z, nrm);
    g_sid[b * NPTS + pos] = n;
}

// ---------------------------------------------------------------------------
// Grid KNN: expanding Chebyshev rings with certified termination.
// key = |m|^2 - 2 q.m  (same formula as previous passing kernels)
// ---------------------------------------------------------------------------
__device__ __forceinline__ void scan_range(const float4* __restrict__ sp,
                                           const int* __restrict__ sid,
                                           int s, int e,
                                           float nx, float ny, float nz,
                                           float bd[KNN], int bi[KNN], float& thr) {
    for (int j = s; j < e; ++j) {
        float4 m = sp[j];
        float d = fmaf(nx, m.x, fmaf(ny, m.y, fmaf(nz, m.z, m.w)));
        if (d < thr) {
            insert16(d, sid[j], bd, bi);
            thr = bd[KNN - 1];
        }
    }
}

__global__ void __launch_bounds__(128) gknn() {
    const int gi = blockIdx.x * 128 + threadIdx.x;
    const int b  = gi >> 13;
    const int si = gi & (NPTS - 1);
    const float4* sp = g_spt + (size_t)b * NPTS;
    const int*   sid = g_sid + (size_t)b * NPTS;
    const int*   cs  = g_cstart + (size_t)b * (G3 + 1);

    float4 q4 = sp[si];
    const float qn = q4.w;
    const float nx = -2.f * q4.x, ny = -2.f * q4.y, nz = -2.f * q4.z;
    const int cx = min(G - 1, max(0, (int)floorf((q4.x - ORG) * HINV)));
    const int cy = min(G - 1, max(0, (int)floorf((q4.y - ORG) * HINV)));
    const int cz = min(G - 1, max(0, (int)floorf((q4.z - ORG) * HINV)));

    float bd[KNN]; int bi[KNN];
#pragma unroll
    for (int j = 0; j < KNN; ++j) { bd[j] = 3.4e38f; bi[j] = 0; }
    float thr = 3.4e38f;

    for (int r = 0; r < G; ++r) {
        if (r >= 1) {
            float rb = (float)(r - 1) * HCELL;
            // all unscanned points have shifted key >= rb*rb - qn (exact bound
            // minus fp slack); stop when the 16th-best cannot be displaced.
            if (bd[KNN - 1] + qn <= rb * rb - 1e-3f) break;
        }
        const int zlo = max(cz - r, 0), zhi = min(cz + r, G - 1);
        const int ylo = max(cy - r, 0), yhi = min(cy + r, G - 1);
        const int xlo = max(cx - r, 0), xhi = min(cx + r, G - 1);
        for (int z = zlo; z <= zhi; ++z) {
            const int adz = abs(z - cz);
            for (int y = ylo; y <= yhi; ++y) {
                const int ady = abs(y - cy);
                const int rowbase = (z * G + y) * G;
                if (max(adz, ady) == r) {
                    // entire x-run belongs to ring r: contiguous cells
                    int s = cs[rowbase + xlo];
                    int e = cs[rowbase + xhi + 1];
                    scan_range(sp, sid, s, e, nx, ny, nz, bd, bi, thr);
                } else {
                    // only the two x-extremes are on ring r
                    if (cx - r >= 0) {
                        int c0 = rowbase + cx - r;
                        scan_range(sp, sid, cs[c0], cs[c0 + 1], nx, ny, nz, bd, bi, thr);
                    }
                    if (cx + r <= G - 1) {
                        int c1 = rowbase + cx + r;
                        scan_range(sp, sid, cs[c1], cs[c1 + 1], nx, ny, nz, bd, bi, thr);
                    }
                }
            }
        }
    }

    const int qorig = sid[si];
    int* op = g_idx + ((size_t)b * NPTS + qorig) * KNN;
#pragma unroll
    for (int j = 0; j < KNN; ++j) op[j] = bi[j];
}

// ---------------------------------------------------------------------------
// Kernel W: precombine weights (no ReLU between pairs -> linear fold)
// ---------------------------------------------------------------------------
__global__ void __launch_bounds__(256) wprep(const float* __restrict__ w_theta1,
                                             const float* __restrict__ w_theta2,
                                             const float* __restrict__ w_gamma1,
                                             const float* __restrict__ w_gamma2) {
    __shared__ float s1[4096], s2[4096];
    const int t = threadIdx.x;
    for (int i = t; i < 4096; i += 256) { s1[i] = w_gamma1[i]; s2[i] = w_gamma2[i]; }
    __syncthreads();
    {
        int i = blockIdx.x * 256 + t;
        int c = i >> 6, o = i & 63;
        float a = 0.f;
#pragma unroll 16
        for (int m = 0; m < 64; ++m) a = fmaf(s2[o * 64 + m], s1[m * 64 + c], a);
        g_WgT[c * 64 + o] = a;
    }
    if (blockIdx.x == 0 && t < 192) {
        int c3 = t / 64, o = t % 64;
        float a = 0.f;
#pragma unroll 16
        for (int m = 0; m < 64; ++m) a = fmaf(w_theta2[o * 64 + m], w_theta1[m * 3 + c3], a);
        g_WtT[c3 * 64 + o] = a;
    }
}

// ---------------------------------------------------------------------------
// Kernel 2: feat3[b,n,o] = sum_c w_lin[o,c] * features[b,c,n]
// ---------------------------------------------------------------------------
__global__ void __launch_bounds__(128) feat3_kernel(const float* __restrict__ features,
                                                    const float* __restrict__ w_lin) {
    __shared__ float sw[F3 * CIN];
    for (int i = threadIdx.x; i < F3 * CIN; i += 128) sw[i] = w_lin[i];

    const int b = blockIdx.y;
    const int n = blockIdx.x * 128 + threadIdx.x;

    float f[CIN];
    const float* fb = features + (size_t)b * CIN * NPTS + n;
#pragma unroll
    for (int c = 0; c < CIN; ++c) f[c] = fb[(size_t)c * NPTS];
    __syncthreads();

    float* outp = g_feat3 + ((size_t)b * NPTS + n) * F3;
    const float4* sw4 = (const float4*)sw;
#pragma unroll 1
    for (int og = 0; og < F3 / 4; ++og) {
        float a0 = 0.f, a1 = 0.f, a2 = 0.f, a3 = 0.f;
#pragma unroll
        for (int c4 = 0; c4 < CIN / 4; ++c4) {
            float4 w0 = sw4[(og * 4 + 0) * 16 + c4];
            float4 w1 = sw4[(og * 4 + 1) * 16 + c4];
            float4 w2 = sw4[(og * 4 + 2) * 16 + c4];
            float4 w3 = sw4[(og * 4 + 3) * 16 + c4];
            int c = c4 * 4;
            a0 = fmaf(w0.x, f[c], fmaf(w0.y, f[c+1], fmaf(w0.z, f[c+2], fmaf(w0.w, f[c+3], a0))));
            a1 = fmaf(w1.x, f[c], fmaf(w1.y, f[c+1], fmaf(w1.z, f[c+2], fmaf(w1.w, f[c+3], a1))));
            a2 = fmaf(w2.x, f[c], fmaf(w2.y, f[c+1], fmaf(w2.z, f[c+2], fmaf(w2.w, f[c+3], a2))));
            a3 = fmaf(w3.x, f[c], fmaf(w3.y, f[c+1], fmaf(w3.z, f[c+2], fmaf(w3.w, f[c+3], a3))));
        }
        ((float4*)outp)[og] = make_float4(a0, a1, a2, a3);
    }
}

// ---------------------------------------------------------------------------
__device__ __forceinline__ void gemm64(ull acc[8], const float* __restrict__ wcolT,
                                       const float* __restrict__ vrow) {
#pragma unroll
    for (int p = 0; p < 8; ++p) acc[p] = 0ull;
#pragma unroll 16
    for (int c = 0; c < 64; ++c) {
        float4 w = *(const float4*)(wcolT + c * 64);
        double2 vv = *(const double2*)(vrow + c * CS);
        ull v0 = __double_as_longlong(vv.x);
        ull v1 = __double_as_longlong(vv.y);
        ull w0 = pack2(w.x), w1 = pack2(w.y), w2 = pack2(w.z), w3 = pack2(w.w);
        fma2(acc[0], w0, v0); fma2(acc[1], w0, v1);
        fma2(acc[2], w1, v0); fma2(acc[3], w1, v1);
        fma2(acc[4], w2, v0); fma2(acc[5], w2, v1);
        fma2(acc[6], w3, v0); fma2(acc[7], w3, v1);
    }
}

#define TEAM_BAR() asm volatile("bar.sync %0, 64;" :: "r"(barid) : "memory")

// ---------------------------------------------------------------------------
// Kernel 3: fused attention (proven version: P-loop, grid 2048)
// ---------------------------------------------------------------------------
#define TA 2560
__global__ void __launch_bounds__(256) fused_kernel(const float* __restrict__ coords,
                                                    float* __restrict__ out) {
    extern __shared__ float sm[];
    float* sWgT = sm;            // 4096  [c][o]
    float* sWtT = sm + 4096;     // 192   [c3][o]

    const int tid = threadIdx.x;
    for (int i = tid; i < 4096; i += 256) sWgT[i] = g_WgT[i];
    if (tid < 192) sWtT[tid] = g_WtT[tid];
    __syncthreads();

    const int gq  = tid >> 6;
    const int t64 = tid & 63;
    const int og  = t64 >> 2;
    const int kg  = t64 & 3;
    const int k    = t64 & 15;
    const int half = t64 >> 4;
    const int barid = gq + 1;

    float* ig = sm + 4288 + gq * TA;   // [64][CS]
    float* AG = ig + 1280;             // [64][CS]

    for (int P = blockIdx.x * PPT + gq; P < NQ; P += gridDim.x * PPT) {
        const int b = P >> 13;
        const int n = P & (NPTS - 1);

        // ---- gather + delta + staging ----
        {
            int ik = g_idx[(size_t)P * KNN + k];
            const float* cb = coords + (size_t)b * 3 * NPTS;
            float rx = cb[n]            - cb[ik];
            float ry = cb[NPTS + n]     - cb[NPTS + ik];
            float rz = cb[2 * NPTS + n] - cb[2 * NPTS + ik];

            const float* fb = g_feat3 + (size_t)(b * NPTS + ik) * F3;
            const float* fq = g_feat3 + (size_t)P * F3;
#pragma unroll
            for (int c4 = 0; c4 < 4; ++c4) {
                int c = half * 16 + c4 * 4;
                float4 ph = *(const float4*)(fq + c);
                float4 ps = *(const float4*)(fb + 64 + c);
                float4 al = *(const float4*)(fb + 128 + c);
                float4 w0 = *(const float4*)(sWtT + c);
                float4 w1 = *(const float4*)(sWtT + 64 + c);
                float4 w2 = *(const float4*)(sWtT + 128 + c);
                float d0 = fmaxf(fmaf(w2.x, rz, fmaf(w1.x, ry, w0.x * rx)), 0.f);
                float d1 = fmaxf(fmaf(w2.y, rz, fmaf(w1.y, ry, w0.y * rx)), 0.f);
                float d2 = fmaxf(fmaf(w2.z, rz, fmaf(w1.z, ry, w0.z * rx)), 0.f);
                float d3 = fmaxf(fmaf(w2.w, rz, fmaf(w1.w, ry, w0.w * rx)), 0.f);
                ig[(c + 0) * CS + k] = ph.x - ps.x + d0;
                ig[(c + 1) * CS + k] = ph.y - ps.y + d1;
                ig[(c + 2) * CS + k] = ph.z - ps.z + d2;
                ig[(c + 3) * CS + k] = ph.w - ps.w + d3;
                AG[(c + 0) * CS + k] = al.x + d0;
                AG[(c + 1) * CS + k] = al.y + d1;
                AG[(c + 2) * CS + k] = al.z + d2;
                AG[(c + 3) * CS + k] = al.w + d3;
            }
        }
        TEAM_BAR();

        // ---- g = relu(Wg @ ig); softmax over k; weighted sum ----
        ull acc[8];
        gemm64(acc, sWgT + 4 * og, ig + 4 * kg);
#pragma unroll
        for (int i = 0; i < 4; ++i) {
            float g0 = fmaxf(f2lo(acc[2*i]),   0.f);
            float g1 = fmaxf(f2hi(acc[2*i]),   0.f);
            float g2 = fmaxf(f2lo(acc[2*i+1]), 0.f);
            float g3 = fmaxf(f2hi(acc[2*i+1]), 0.f);
            float m = fmaxf(fmaxf(g0, g1), fmaxf(g2, g3));
            m = fmaxf(m, __shfl_xor_sync(0xffffffffu, m, 1));
            m = fmaxf(m, __shfl_xor_sync(0xffffffffu, m, 2));
            float e0 = __expf(g0 - m), e1 = __expf(g1 - m);
            float e2 = __expf(g2 - m), e3 = __expf(g3 - m);
            float s = (e0 + e1) + (e2 + e3);
            float4 a = *(const float4*)&AG[(4 * og + i) * CS + 4 * kg];
            float num = fmaf(e0, a.x, fmaf(e1, a.y, fmaf(e2, a.z, e3 * a.w)));
            s   += __shfl_xor_sync(0xffffffffu, s, 1);
            num += __shfl_xor_sync(0xffffffffu, num, 1);
            s   += __shfl_xor_sync(0xffffffffu, s, 2);
            num += __shfl_xor_sync(0xffffffffu, num, 2);
            if (kg == 0)
                out[((size_t)b * CO + 4 * og + i) * NPTS + n] = num / s;
        }
        TEAM_BAR();
    }
}

// ---------------------------------------------------------------------------
#define FUSED_SMEM ((4288 + PPT * TA) * sizeof(float))
extern "C" void kernel_launch(void* const* d_in, const int* in_sizes, int n_in,
                              void* d_out, int out_size) {
    const float* features = (const float*)d_in[0];
    const float* coords   = (const float*)d_in[1];
    const float* w_lin    = (const float*)d_in[2];
    const float* w_theta1 = (const float*)d_in[3];
    const float* w_theta2 = (const float*)d_in[4];
    const float* w_gamma1 = (const float*)d_in[5];
    const float* w_gamma2 = (const float*)d_in[6];
    float* out = (float*)d_out;

    static bool attr_set = false;
    if (!attr_set) {
        cudaFuncSetAttribute(fused_kernel, cudaFuncAttributeMaxDynamicSharedMemorySize,
                             FUSED_SMEM);
        attr_set = true;
    }

    // grid build + knn
    gzero<<<(BATCH * G3) / 256, 256>>>();
    gcount<<<dim3(NPTS / 256, BATCH), 256>>>(coords);
    gscan<<<BATCH, 1024>>>();
    gfill<<<dim3(NPTS / 256, BATCH), 256>>>(coords);
    gknn<<<NQ / 128, 128>>>();

    // independent prep
    wprep<<<16, 256>>>(w_theta1, w_theta2, w_gamma1, w_gamma2);
    feat3_kernel<<<dim3(NPTS / 128, BATCH), 128>>>(features, w_lin);

    // fused attention
    fused_kernel<<<2048, 256, FUSED_SMEM>>>(coords, out);
}

// round 13
// speedup vs baseline: 1.1142x; 1.1142x over previous
#include <cuda_runtime.h>
#include <cstdint>

#define BATCH 4
#define NPTS  8192
#define KNN   16
#define CIN   64
#define CO    64
#define F3    192
#define CS    20
#define PPT   4
#define NQ    (BATCH * NPTS)

// grid params
#define G     32
#define G3    (G * G * G)
#define HCELL 0.25f
#define HINV  4.0f
#define ORG   (-4.0f)

#define BIGF  3.4e38f

typedef unsigned long long ull;
typedef unsigned int uint;

__device__ int    g_idx[NQ * KNN];
__device__ float  g_feat3[(size_t)NQ * F3];
__device__ float  g_WgT[CO * CO];   // [c][o] = (w_gamma2 @ w_gamma1)^T
__device__ float  g_WtT[3 * CO];    // [c3][o] = (w_theta2 @ w_theta1)^T

// grid scratch
__device__ int    g_cnt[BATCH * G3];
__device__ int    g_cstart[BATCH * (G3 + 1)];
__device__ int    g_ccur[BATCH * G3];
__device__ int    g_cid[BATCH * NPTS];
__device__ float4 g_spt[BATCH * NPTS];   // cell-sorted points {x,y,z,|p|^2}
__device__ int    g_sid[BATCH * NPTS];   // original index of sorted point

// ---------------------------------------------------------------------------
// packed f32x2 helpers (fused kernel)
// ---------------------------------------------------------------------------
__device__ __forceinline__ ull pack2(float f) {
    ull r; uint u = __float_as_uint(f);
    asm("mov.b64 %0, {%1, %1};" : "=l"(r) : "r"(u));
    return r;
}
__device__ __forceinline__ void fma2(ull& acc, ull a, ull b) {
    asm("fma.rn.f32x2 %0, %1, %2, %0;" : "+l"(acc) : "l"(a), "l"(b));
}
__device__ __forceinline__ float f2lo(ull v) { return __uint_as_float((uint)v); }
__device__ __forceinline__ float f2hi(ull v) { return __uint_as_float((uint)(v >> 32)); }

// ---------------------------------------------------------------------------
// Grid build kernels
// ---------------------------------------------------------------------------
__global__ void __launch_bounds__(256) gzero() {
    int i = blockIdx.x * 256 + threadIdx.x;
    if (i < BATCH * G3) g_cnt[i] = 0;
}

__device__ __forceinline__ int cell_of(float x, float y, float z) {
    int cx = min(G - 1, max(0, (int)floorf((x - ORG) * HINV)));
    int cy = min(G - 1, max(0, (int)floorf((y - ORG) * HINV)));
    int cz = min(G - 1, max(0, (int)floorf((z - ORG) * HINV)));
    return (cz * G + cy) * G + cx;
}

__global__ void __launch_bounds__(256) gcount(const float* __restrict__ coords) {
    const int b = blockIdx.y;
    const int n = blockIdx.x * 256 + threadIdx.x;
    const float* cb = coords + (size_t)b * 3 * NPTS;
    float x = cb[n], y = cb[NPTS + n], z = cb[2 * NPTS + n];
    int cid = cell_of(x, y, z);
    g_cid[b * NPTS + n] = cid;
    atomicAdd(&g_cnt[b * G3 + cid], 1);
}

// per-batch exclusive prefix scan over G3 counts (1024 threads x 32 cells)
__global__ void __launch_bounds__(1024) gscan() {
    __shared__ int part[1024];
    const int b = blockIdx.x;
    const int t = threadIdx.x;
    const int base = b * G3 + t * 32;

    int s = 0;
#pragma unroll 8
    for (int i = 0; i < 32; ++i) s += g_cnt[base + i];
    part[t] = s;
    __syncthreads();
    for (int off = 1; off < 1024; off <<= 1) {
        int v = (t >= off) ? part[t - off] : 0;
        __syncthreads();
        part[t] += v;
        __syncthreads();
    }
    int run = part[t] - s;   // exclusive prefix of this thread's chunk
    const int obase = b * (G3 + 1) + t * 32;
#pragma unroll 8
    for (int i = 0; i < 32; ++i) {
        int c = g_cnt[base + i];
        g_cstart[obase + i] = run;
        g_ccur[base + i] = run;
        run += c;
    }
    if (t == 1023) g_cstart[b * (G3 + 1) + G3] = part[1023];
}

__global__ void __launch_bounds__(256) gfill(const float* __restrict__ coords) {
    const int b = blockIdx.y;
    const int n = blockIdx.x * 256 + threadIdx.x;
    const float* cb = coords + (size_t)b * 3 * NPTS;
    float x = cb[n], y = cb[NPTS + n], z = cb[2 * NPTS + n];
    int cid = g_cid[b * NPTS + n];
    int pos = atomicAdd(&g_ccur[b * G3 + cid], 1);
    float nrm = fmaf(z, z, fmaf(y, y, x * x));
    g_spt[b * NPTS + pos] = make_float4(x, y, z, nrm);
    g_sid[b * NPTS + pos] = n;
}

// ---------------------------------------------------------------------------
// Warp-cooperative grid KNN. One warp per query.
// Top-16 distributed: lanes 0..15 each hold one (d, idx) slot.
// key = |m|^2 - 2 q.m  (same formula as all previous passing kernels)
// ---------------------------------------------------------------------------
struct WTop {
    float bd;      // this lane's slot (lanes 0..15), BIGF initially
    int   bi;
    float thr;     // warp-uniform: max over the 16 slots
    int   maxlane; // warp-uniform: lane holding thr
};

__device__ __forceinline__ void wtop_recompute(WTop& w, int lane) {
    float v = (lane < KNN) ? w.bd : -BIGF;
    int   l = lane;
#pragma unroll
    for (int off = 16; off; off >>= 1) {
        float ov = __shfl_xor_sync(0xffffffffu, v, off);
        int   ol = __shfl_xor_sync(0xffffffffu, l, off);
        if (ov > v || (ov == v && ol < l)) { v = ov; l = ol; }
    }
    w.thr = v; w.maxlane = l;
}

// scan candidate range [s,e); 32 lanes in parallel
__device__ __forceinline__ void wscan_range(const float4* __restrict__ sp,
                                            const int* __restrict__ sid,
                                            int s, int e,
                                            float nx, float ny, float nz,
                                            WTop& w, int lane) {
    for (int j0 = s; j0 < e; j0 += 32) {
        int j = j0 + lane;
        float d = BIGF; int id = 0;
        if (j < e) {
            float4 m = sp[j];
            d  = fmaf(nx, m.x, fmaf(ny, m.y, fmaf(nz, m.z, m.w)));
            id = sid[j];
        }
        uint mask = __ballot_sync(0xffffffffu, d < w.thr);
        while (mask) {
            int src = __ffs(mask) - 1;
            mask &= mask - 1;
            float dd = __shfl_sync(0xffffffffu, d,  src);
            int   ii = __shfl_sync(0xffffffffu, id, src);
            if (dd < w.thr) {
                if (lane == w.maxlane) { w.bd = dd; w.bi = ii; }
                wtop_recompute(w, lane);
            }
        }
    }
}

__global__ void __launch_bounds__(256) gknn() {
    const int wid  = (blockIdx.x * 256 + threadIdx.x) >> 5;   // one warp = one query
    const int lane = threadIdx.x & 31;
    const int b  = wid >> 13;
    const int si = wid & (NPTS - 1);
    const float4* sp = g_spt + (size_t)b * NPTS;
    const int*   sid = g_sid + (size_t)b * NPTS;
    const int*   cs  = g_cstart + (size_t)b * (G3 + 1);

    float4 q4 = sp[si];
    const float qn = q4.w;
    const float nx = -2.f * q4.x, ny = -2.f * q4.y, nz = -2.f * q4.z;
    const int cx = min(G - 1, max(0, (int)floorf((q4.x - ORG) * HINV)));
    const int cy = min(G - 1, max(0, (int)floorf((q4.y - ORG) * HINV)));
    const int cz = min(G - 1, max(0, (int)floorf((q4.z - ORG) * HINV)));

    WTop w;
    w.bd = BIGF; w.bi = 0; w.thr = BIGF; w.maxlane = 0;

    for (int r = 0; r < G; ++r) {
        if (r >= 1) {
            float rb = (float)(r - 1) * HCELL;
            // unscanned points have key >= rb*rb - qn (exact; clamped cells only
            // push true positions farther out). Stop when 16th-best is safe.
            if (w.thr + qn <= rb * rb - 1e-3f) break;
        }
        const int zlo = max(cz - r, 0), zhi = min(cz + r, G - 1);
        const int ylo = max(cy - r, 0), yhi = min(cy + r, G - 1);
        const int xlo = max(cx - r, 0), xhi = min(cx + r, G - 1);
        for (int z = zlo; z <= zhi; ++z) {
            const int adz = abs(z - cz);
            for (int y = ylo; y <= yhi; ++y) {
                const int ady = abs(y - cy);
                const int rowbase = (z * G + y) * G;
                if (max(adz, ady) == r) {
                    // full contiguous x-run on ring r
                    int s = cs[rowbase + xlo];
                    int e = cs[rowbase + xhi + 1];
                    wscan_range(sp, sid, s, e, nx, ny, nz, w, lane);
                } else {
                    if (cx - r >= 0) {
                        int c0 = rowbase + cx - r;
                        wscan_range(sp, sid, cs[c0], cs[c0 + 1], nx, ny, nz, w, lane);
                    }
                    if (cx + r <= G - 1) {
                        int c1 = rowbase + cx + r;
                        wscan_range(sp, sid, cs[c1], cs[c1 + 1], nx, ny, nz, w, lane);
                    }
                }
            }
        }
    }

    // write the 16 (order arbitrary: downstream reduces over k permutation-invariantly)
    const int qorig = sid[si];
    if (lane < KNN)
        g_idx[((size_t)b * NPTS + qorig) * KNN + lane] = w.bi;
}

// ---------------------------------------------------------------------------
// Kernel W: precombine weights (no ReLU between pairs -> linear fold)
// ---------------------------------------------------------------------------
__global__ void __launch_bounds__(256) wprep(const float* __restrict__ w_theta1,
                                             const float* __restrict__ w_theta2,
                                             const float* __restrict__ w_gamma1,
                                             const float* __restrict__ w_gamma2) {
    __shared__ float s1[4096], s2[4096];
    const int t = threadIdx.x;
    for (int i = t; i < 4096; i += 256) { s1[i] = w_gamma1[i]; s2[i] = w_gamma2[i]; }
    __syncthreads();
    {
        int i = blockIdx.x * 256 + t;
        int c = i >> 6, o = i & 63;
        float a = 0.f;
#pragma unroll 16
        for (int m = 0; m < 64; ++m) a = fmaf(s2[o * 64 + m], s1[m * 64 + c], a);
        g_WgT[c * 64 + o] = a;
    }
    if (blockIdx.x == 0 && t < 192) {
        int c3 = t / 64, o = t % 64;
        float a = 0.f;
#pragma unroll 16
        for (int m = 0; m < 64; ++m) a = fmaf(w_theta2[o * 64 + m], w_theta1[m * 3 + c3], a);
        g_WtT[c3 * 64 + o] = a;
    }
}

// ---------------------------------------------------------------------------
// Kernel 2: feat3[b,n,o] = sum_c w_lin[o,c] * features[b,c,n]
// ---------------------------------------------------------------------------
__global__ void __launch_bounds__(128) feat3_kernel(const float* __restrict__ features,
                                                    const float* __restrict__ w_lin) {
    __shared__ float sw[F3 * CIN];
    for (int i = threadIdx.x; i < F3 * CIN; i += 128) sw[i] = w_lin[i];

    const int b = blockIdx.y;
    const int n = blockIdx.x * 128 + threadIdx.x;

    float f[CIN];
    const float* fb = features + (size_t)b * CIN * NPTS + n;
#pragma unroll
    for (int c = 0; c < CIN; ++c) f[c] = fb[(size_t)c * NPTS];
    __syncthreads();

    float* outp = g_feat3 + ((size_t)b * NPTS + n) * F3;
    const float4* sw4 = (const float4*)sw;
#pragma unroll 1
    for (int og = 0; og < F3 / 4; ++og) {
        float a0 = 0.f, a1 = 0.f, a2 = 0.f, a3 = 0.f;
#pragma unroll
        for (int c4 = 0; c4 < CIN / 4; ++c4) {
            float4 w0 = sw4[(og * 4 + 0) * 16 + c4];
            float4 w1 = sw4[(og * 4 + 1) * 16 + c4];
            float4 w2 = sw4[(og * 4 + 2) * 16 + c4];
            float4 w3 = sw4[(og * 4 + 3) * 16 + c4];
            int c = c4 * 4;
            a0 = fmaf(w0.x, f[c], fmaf(w0.y, f[c+1], fmaf(w0.z, f[c+2], fmaf(w0.w, f[c+3], a0))));
            a1 = fmaf(w1.x, f[c], fmaf(w1.y, f[c+1], fmaf(w1.z, f[c+2], fmaf(w1.w, f[c+3], a1))));
            a2 = fmaf(w2.x, f[c], fmaf(w2.y, f[c+1], fmaf(w2.z, f[c+2], fmaf(w2.w, f[c+3], a2))));
            a3 = fmaf(w3.x, f[c], fmaf(w3.y, f[c+1], fmaf(w3.z, f[c+2], fmaf(w3.w, f[c+3], a3))));
        }
        ((float4*)outp)[og] = make_float4(a0, a1, a2, a3);
    }
}

// ---------------------------------------------------------------------------
__device__ __forceinline__ void gemm64(ull acc[8], const float* __restrict__ wcolT,
                                       const float* __restrict__ vrow) {
#pragma unroll
    for (int p = 0; p < 8; ++p) acc[p] = 0ull;
#pragma unroll 16
    for (int c = 0; c < 64; ++c) {
        float4 w = *(const float4*)(wcolT + c * 64);
        double2 vv = *(const double2*)(vrow + c * CS);
        ull v0 = __double_as_longlong(vv.x);
        ull v1 = __double_as_longlong(vv.y);
        ull w0 = pack2(w.x), w1 = pack2(w.y), w2 = pack2(w.z), w3 = pack2(w.w);
        fma2(acc[0], w0, v0); fma2(acc[1], w0, v1);
        fma2(acc[2], w1, v0); fma2(acc[3], w1, v1);
        fma2(acc[4], w2, v0); fma2(acc[5], w2, v1);
        fma2(acc[6], w3, v0); fma2(acc[7], w3, v1);
    }
}

#define TEAM_BAR() asm volatile("bar.sync %0, 64;" :: "r"(barid) : "memory")

// ---------------------------------------------------------------------------
// Kernel 3: fused attention (proven version: P-loop, grid 2048)
// ---------------------------------------------------------------------------
#define TA 2560
__global__ void __launch_bounds__(256) fused_kernel(const float* __restrict__ coords,
                                                    float* __restrict__ out) {
    extern __shared__ float sm[];
    float* sWgT = sm;            // 4096  [c][o]
    float* sWtT = sm + 4096;     // 192   [c3][o]

    const int tid = threadIdx.x;
    for (int i = tid; i < 4096; i += 256) sWgT[i] = g_WgT[i];
    if (tid < 192) sWtT[tid] = g_WtT[tid];
    __syncthreads();

    const int gq  = tid >> 6;
    const int t64 = tid & 63;
    const int og  = t64 >> 2;
    const int kg  = t64 & 3;
    const int k    = t64 & 15;
    const int half = t64 >> 4;
    const int barid = gq + 1;

    float* ig = sm + 4288 + gq * TA;   // [64][CS]
    float* AG = ig + 1280;             // [64][CS]

    for (int P = blockIdx.x * PPT + gq; P < NQ; P += gridDim.x * PPT) {
        const int b = P >> 13;
        const int n = P & (NPTS - 1);

        // ---- gather + delta + staging ----
        {
            int ik = g_idx[(size_t)P * KNN + k];
            const float* cb = coords + (size_t)b * 3 * NPTS;
            float rx = cb[n]            - cb[ik];
            float ry = cb[NPTS + n]     - cb[NPTS + ik];
            float rz = cb[2 * NPTS + n] - cb[2 * NPTS + ik];

            const float* fb = g_feat3 + (size_t)(b * NPTS + ik) * F3;
            const float* fq = g_feat3 + (size_t)P * F3;
#pragma unroll
            for (int c4 = 0; c4 < 4; ++c4) {
                int c = half * 16 + c4 * 4;
                float4 ph = *(const float4*)(fq + c);
                float4 ps = *(const float4*)(fb + 64 + c);
                float4 al = *(const float4*)(fb + 128 + c);
                float4 w0 = *(const float4*)(sWtT + c);
                float4 w1 = *(const float4*)(sWtT + 64 + c);
                float4 w2 = *(const float4*)(sWtT + 128 + c);
                float d0 = fmaxf(fmaf(w2.x, rz, fmaf(w1.x, ry, w0.x * rx)), 0.f);
                float d1 = fmaxf(fmaf(w2.y, rz, fmaf(w1.y, ry, w0.y * rx)), 0.f);
                float d2 = fmaxf(fmaf(w2.z, rz, fmaf(w1.z, ry, w0.z * rx)), 0.f);
                float d3 = fmaxf(fmaf(w2.w, rz, fmaf(w1.w, ry, w0.w * rx)), 0.f);
                ig[(c + 0) * CS + k] = ph.x - ps.x + d0;
                ig[(c + 1) * CS + k] = ph.y - ps.y + d1;
                ig[(c + 2) * CS + k] = ph.z - ps.z + d2;
                ig[(c + 3) * CS + k] = ph.w - ps.w + d3;
                AG[(c + 0) * CS + k] = al.x + d0;
                AG[(c + 1) * CS + k] = al.y + d1;
                AG[(c + 2) * CS + k] = al.z + d2;
                AG[(c + 3) * CS + k] = al.w + d3;
            }
        }
        TEAM_BAR();

        // ---- g = relu(Wg @ ig); softmax over k; weighted sum ----
        ull acc[8];
        gemm64(acc, sWgT + 4 * og, ig + 4 * kg);
#pragma unroll
        for (int i = 0; i < 4; ++i) {
            float g0 = fmaxf(f2lo(acc[2*i]),   0.f);
            float g1 = fmaxf(f2hi(acc[2*i]),   0.f);
            float g2 = fmaxf(f2lo(acc[2*i+1]), 0.f);
            float g3 = fmaxf(f2hi(acc[2*i+1]), 0.f);
            float m = fmaxf(fmaxf(g0, g1), fmaxf(g2, g3));
            m = fmaxf(m, __shfl_xor_sync(0xffffffffu, m, 1));
            m = fmaxf(m, __shfl_xor_sync(0xffffffffu, m, 2));
            float e0 = __expf(g0 - m), e1 = __expf(g1 - m);
            float e2 = __expf(g2 - m), e3 = __expf(g3 - m);
            float s = (e0 + e1) + (e2 + e3);
            float4 a = *(const float4*)&AG[(4 * og + i) * CS + 4 * kg];
            float num = fmaf(e0, a.x, fmaf(e1, a.y, fmaf(e2, a.z, e3 * a.w)));
            s   += __shfl_xor_sync(0xffffffffu, s, 1);
            num += __shfl_xor_sync(0xffffffffu, num, 1);
            s   += __shfl_xor_sync(0xffffffffu, s, 2);
            num += __shfl_xor_sync(0xffffffffu, num, 2);
            if (kg == 0)
                out[((size_t)b * CO + 4 * og + i) * NPTS + n] = num / s;
        }
        TEAM_BAR();
    }
}

// ---------------------------------------------------------------------------
#define FUSED_SMEM ((4288 + PPT * TA) * sizeof(float))
extern "C" void kernel_launch(void* const* d_in, const int* in_sizes, int n_in,
                              void* d_out, int out_size) {
    const float* features = (const float*)d_in[0];
    const float* coords   = (const float*)d_in[1];
    const float* w_lin    = (const float*)d_in[2];
    const float* w_theta1 = (const float*)d_in[3];
    const float* w_theta2 = (const float*)d_in[4];
    const float* w_gamma1 = (const float*)d_in[5];
    const float* w_gamma2 = (const float*)d_in[6];
    float* out = (float*)d_out;

    static bool attr_set = false;
    if (!attr_set) {
        cudaFuncSetAttribute(fused_kernel, cudaFuncAttributeMaxDynamicSharedMemorySize,
                             FUSED_SMEM);
        attr_set = true;
    }

    // grid build + warp-cooperative knn
    gzero<<<(BATCH * G3) / 256, 256>>>();
    gcount<<<dim3(NPTS / 256, BATCH), 256>>>(coords);
    gscan<<<BATCH, 1024>>>();
    gfill<<<dim3(NPTS / 256, BATCH), 256>>>(coords);
    gknn<<<NQ / 8, 256>>>();

    // independent prep
    wprep<<<16, 256>>>(w_theta1, w_theta2, w_gamma1, w_gamma2);
    feat3_kernel<<<dim3(NPTS / 128, BATCH), 128>>>(features, w_lin);

    // fused attention
    fused_kernel<<<2048, 256, FUSED_SMEM>>>(coords, out);
}